// round 1
// baseline (speedup 1.0000x reference)
#include <cuda_runtime.h>
#include <cuda_bf16.h>
#include <cstdint>

// ---------------------------------------------------------------------------
// DCNv2: offset/mask conv (3x3, stride 2, pad 1) + modulated deformable gather
//   x        : (2, 128, 256, 256) f32
//   w_offset : (1152, 128, 3, 3)   b_offset : (1152,)
//   w_mask   : (576, 128, 3, 3)    b_mask   : (576,)
//   w_deform : (128, 2, 3, 3)
//   out      : (2, 128, 128, 128) f32
// Stage A: fused conv producing 1728 channels (offset raw, mask sigmoid'ed)
// Stage B: bilinear gather + per-group (2x2x9) matmul
// ---------------------------------------------------------------------------

#define B_      2
#define C_      128
#define H_      256
#define W_      256
#define HO_     128
#define WO_     128
#define G_      64
#define K_      9
#define OC_OFF  1152         // offset channels
#define OC_ALL  1728         // offset + mask channels

#define TOC     128          // out channels per block tile
#define CIN_T   4            // input channels per k-chunk
#define XS_W    260          // padded patch width (257 used)

// 226.5 MB scratch for conv output (B, 1728, 128, 128)
__device__ float g_conv[(size_t)B_ * OC_ALL * HO_ * WO_];

// ---------------------------------------------------------------------------
// Stage A: direct conv, block = 256 thr, tile = 128 och x 128 wo (one row)
// thread tile = 8 och x 8 wo  ->  FMA:LDS ratio 4
// ---------------------------------------------------------------------------
__global__ __launch_bounds__(256, 2)
void conv_offmask_kernel(const float* __restrict__ x,
                         const float* __restrict__ w_off,
                         const float* __restrict__ b_off,
                         const float* __restrict__ w_msk,
                         const float* __restrict__ b_msk)
{
    __shared__ float ws[CIN_T][9][TOC];    // [ci][k][oc_local]  18.0 KB
    __shared__ float xs[CIN_T][3][XS_W];   // [ci][ky][col]      12.2 KB

    const int rt      = blockIdx.x;        // (b, ho) row tile: 0..255
    const int b       = rt >> 7;
    const int ho      = rt & 127;
    const int oc_base = blockIdx.y * TOC;

    const int t  = threadIdx.x;
    const int og = t >> 4;                 // 0..15 : och sub-tile
    const int pg = t & 15;                 // 0..15 : pixel sub-tile

    float acc[8][8];
#pragma unroll
    for (int j = 0; j < 8; ++j)
#pragma unroll
        for (int i = 0; i < 8; ++i) acc[j][i] = 0.f;

    const int iy0 = 2 * ho - 1;

    for (int cc = 0; cc < C_ / CIN_T; ++cc) {
        __syncthreads();

        // ---- load weights for this (oc tile, cin chunk): 4608 floats ----
        for (int idx = t; idx < CIN_T * 9 * TOC; idx += 256) {
            const int ocl = idx / 36;          // 36 = CIN_T*9 floats per oc
            const int j   = idx - ocl * 36;
            const int ci  = j / 9;
            const int k   = j - ci * 9;
            const int oc  = oc_base + ocl;
            const int cin = cc * CIN_T + ci;
            float v = 0.f;
            if (oc < OC_OFF)
                v = w_off[((size_t)oc * C_ + cin) * 9 + k];
            else if (oc < OC_ALL)
                v = w_msk[((size_t)(oc - OC_OFF) * C_ + cin) * 9 + k];
            ws[ci][k][ocl] = v;
        }

        // ---- load input patch: 4 cin x 3 rows x 257 cols ----
        for (int idx = t; idx < CIN_T * 3 * 257; idx += 256) {
            const int ci  = idx / (3 * 257);
            const int r   = idx - ci * (3 * 257);
            const int ky  = r / 257;
            const int col = r - ky * 257;
            const int iy  = iy0 + ky;
            const int ix  = col - 1;
            float v = 0.f;
            if ((unsigned)iy < (unsigned)H_ && (unsigned)ix < (unsigned)W_)
                v = x[(((size_t)b * C_ + cc * CIN_T + ci) * H_ + iy) * W_ + ix];
            xs[ci][ky][col] = v;
        }
        __syncthreads();

        // ---- compute: 4 cin x 9 taps x (8 och x 8 px) FMAs ----
#pragma unroll
        for (int ci = 0; ci < CIN_T; ++ci) {
#pragma unroll
            for (int ky = 0; ky < 3; ++ky) {
#pragma unroll
                for (int kx = 0; kx < 3; ++kx) {
                    const float4 w0 = *(const float4*)&ws[ci][ky * 3 + kx][og * 8];
                    const float4 w1 = *(const float4*)&ws[ci][ky * 3 + kx][og * 8 + 4];
                    float wr[8] = {w0.x, w0.y, w0.z, w0.w, w1.x, w1.y, w1.z, w1.w};
                    float xr[8];
#pragma unroll
                    for (int i = 0; i < 8; ++i)
                        xr[i] = xs[ci][ky][2 * (pg + 16 * i) + kx];
#pragma unroll
                    for (int j = 0; j < 8; ++j)
#pragma unroll
                        for (int i = 0; i < 8; ++i)
                            acc[j][i] = fmaf(wr[j], xr[i], acc[j][i]);
                }
            }
        }
    }

    // ---- epilogue: bias (+ sigmoid for mask channels), store ----
#pragma unroll
    for (int j = 0; j < 8; ++j) {
        const int oc = oc_base + og * 8 + j;
        if (oc >= OC_ALL) continue;
        const bool  is_mask = (oc >= OC_OFF);
        const float bias    = is_mask ? b_msk[oc - OC_OFF] : b_off[oc];
        float* dst = g_conv + (((size_t)b * OC_ALL + oc) * HO_ + ho) * WO_;
#pragma unroll
        for (int i = 0; i < 8; ++i) {
            float v = acc[j][i] + bias;
            if (is_mask) v = 1.f / (1.f + __expf(-v));
            dst[pg + 16 * i] = v;
        }
    }
}

// ---------------------------------------------------------------------------
// Stage B: modulated deformable gather + per-group 2x2x9 matmul
// block = 128 threads (one wo row), grid = B*G*Ho = 16384
// ---------------------------------------------------------------------------
__global__ __launch_bounds__(128)
void deform_kernel(const float* __restrict__ x,
                   const float* __restrict__ w_deform,
                   float* __restrict__ out)
{
    const int blk = blockIdx.x;
    const int ho  = blk & 127;
    const int g   = (blk >> 7) & 63;
    const int b   = blk >> 13;
    const int wo  = threadIdx.x;

    __shared__ float wd[2][2][9];          // [o][c][k]
    if (threadIdx.x < 36) {
        const int o = threadIdx.x / 18;
        const int c = (threadIdx.x / 9) & 1;
        const int k = threadIdx.x % 9;
        wd[o][c][k] = w_deform[(((size_t)(g * 2 + o)) * 2 + c) * 9 + k];
    }
    __syncthreads();

    const float* xg0 = x + ((size_t)(b * C_ + g * 2) * H_) * W_;
    const float* xg1 = xg0 + (size_t)H_ * W_;

    const size_t CS   = (size_t)HO_ * WO_;                     // channel stride
    const size_t pix  = (size_t)ho * WO_ + wo;
    const float* cv_b = g_conv + (size_t)b * OC_ALL * CS + pix;

    float acc0 = 0.f, acc1 = 0.f;

#pragma unroll
    for (int k = 0; k < 9; ++k) {
        const int  choff = (g * K_ + k) * 2;
        const float dy = cv_b[(size_t)choff * CS];
        const float dx = cv_b[(size_t)(choff + 1) * CS];
        const float m  = cv_b[(size_t)(OC_OFF + g * K_ + k) * CS];

        const int ki = k / 3, kj = k - ki * 3;
        const float py = dy + (float)(2 * ho - 1 + ki);
        const float px = dx + (float)(2 * wo - 1 + kj);

        const float y0f = floorf(py), x0f = floorf(px);
        const float wy = py - y0f, wx = px - x0f;
        const int y0 = (int)y0f, x0 = (int)x0f;
        const int y1 = y0 + 1,  x1 = x0 + 1;

        const bool vy0 = (unsigned)y0 < (unsigned)H_;
        const bool vy1 = (unsigned)y1 < (unsigned)H_;
        const bool vx0 = (unsigned)x0 < (unsigned)W_;
        const bool vx1 = (unsigned)x1 < (unsigned)W_;

        const float w00 = (1.f - wy) * (1.f - wx);
        const float w01 = (1.f - wy) * wx;
        const float w10 = wy * (1.f - wx);
        const float w11 = wy * wx;

        const int i00 = y0 * W_ + x0;
        const int i01 = y0 * W_ + x1;
        const int i10 = y1 * W_ + x0;
        const int i11 = y1 * W_ + x1;

        float s0 = 0.f, s1 = 0.f;
        if (vy0 && vx0) { s0 += w00 * xg0[i00]; s1 += w00 * xg1[i00]; }
        if (vy0 && vx1) { s0 += w01 * xg0[i01]; s1 += w01 * xg1[i01]; }
        if (vy1 && vx0) { s0 += w10 * xg0[i10]; s1 += w10 * xg1[i10]; }
        if (vy1 && vx1) { s0 += w11 * xg0[i11]; s1 += w11 * xg1[i11]; }

        s0 *= m; s1 *= m;
        acc0 = fmaf(s0, wd[0][0][k], acc0);
        acc0 = fmaf(s1, wd[0][1][k], acc0);
        acc1 = fmaf(s0, wd[1][0][k], acc1);
        acc1 = fmaf(s1, wd[1][1][k], acc1);
    }

    float* o0 = out + (((size_t)b * C_ + g * 2) * HO_ + ho) * WO_ + wo;
    o0[0]  = acc0;
    o0[CS] = acc1;
}

// ---------------------------------------------------------------------------
extern "C" void kernel_launch(void* const* d_in, const int* in_sizes, int n_in,
                              void* d_out, int out_size)
{
    const float* x        = (const float*)d_in[0];
    const float* w_offset = (const float*)d_in[1];
    const float* b_offset = (const float*)d_in[2];
    const float* w_mask   = (const float*)d_in[3];
    const float* b_mask   = (const float*)d_in[4];
    const float* w_deform = (const float*)d_in[5];
    float* out = (float*)d_out;

    // Stage A: conv -> g_conv (offsets raw + mask sigmoid)
    dim3 gridA(B_ * HO_, (OC_ALL + TOC - 1) / TOC);   // 256 x 14
    conv_offmask_kernel<<<gridA, 256>>>(x, w_offset, b_offset, w_mask, b_mask);

    // Stage B: deformable gather + group matmul
    deform_kernel<<<B_ * G_ * HO_, 128>>>(x, w_deform, out);
}

// round 3
// speedup vs baseline: 4.4917x; 4.4917x over previous
#include <cuda_runtime.h>
#include <cstdint>

// ---------------------------------------------------------------------------
// DCNv2 on GB300 (compute_103 PTX target -> no tcgen05; use mma.sync tf32):
//   Stage P: pack weights -> g_wpack [1792, 1152], tf32-rounded
//   Stage I: im2col x -> g_cols [32768, 1152], tf32-rounded
//   Stage G: mma.sync.m16n8k8 tf32 GEMM D[1728, 32768] = W x cols,
//            fused bias/sigmoid, -> g_conv[b][oc][pix]
//   Stage D: bilinear deformable gather + per-group 2x2x9 matmul
// ---------------------------------------------------------------------------

#define B_      2
#define C_      128
#define H_      256
#define W_      256
#define HO_     128
#define WO_     128
#define G_      64
#define OC_OFF  1152
#define OC_ALL  1728
#define KDIM    1152
#define NPIX    32768
#define MPAD    1792

__device__ __align__(1024) float g_conv[(size_t)B_ * OC_ALL * HO_ * WO_];
__device__ __align__(1024) float g_cols[(size_t)NPIX * KDIM];
__device__ __align__(1024) float g_wpack[(size_t)MPAD * KDIM];

// ------------------------------- helpers ----------------------------------
__device__ __forceinline__ float tf32r(float v) {
    uint32_t o;
    asm("cvt.rna.tf32.f32 %0, %1;" : "=r"(o) : "f"(v));
    return __uint_as_float(o);
}
__device__ __forceinline__ uint32_t smem_u32(const void* p) {
    uint32_t a;
    asm("{ .reg .u64 t; cvta.to.shared.u64 t, %1; cvt.u32.u64 %0, t; }" : "=r"(a) : "l"(p));
    return a;
}
#define CP_ASYNC16(dst, src) \
    asm volatile("cp.async.cg.shared.global [%0], [%1], 16;" :: "r"(dst), "l"(src) : "memory")
#define CP_COMMIT() asm volatile("cp.async.commit_group;" ::: "memory")
#define CP_WAIT(n)  asm volatile("cp.async.wait_group %0;" :: "n"(n) : "memory")

#define MMA_TF32(d, a, b)                                                      \
    asm volatile("mma.sync.aligned.m16n8k8.row.col.f32.tf32.tf32.f32 "         \
        "{%0,%1,%2,%3}, {%4,%5,%6,%7}, {%8,%9}, {%0,%1,%2,%3};"                \
        : "+f"((d)[0]), "+f"((d)[1]), "+f"((d)[2]), "+f"((d)[3])               \
        : "r"(__float_as_uint((a)[0])), "r"(__float_as_uint((a)[1])),          \
          "r"(__float_as_uint((a)[2])), "r"(__float_as_uint((a)[3])),          \
          "r"(__float_as_uint((b)[0])), "r"(__float_as_uint((b)[1])))

// ---------------------------------------------------------------------------
// Stage P: pack + tf32-round weights. rows >= 1728 zero.
// ---------------------------------------------------------------------------
__global__ __launch_bounds__(256)
void pack_w(const float* __restrict__ wo, const float* __restrict__ wm)
{
    const size_t i = (size_t)blockIdx.x * 256 + threadIdx.x;
    if (i >= (size_t)MPAD * KDIM) return;
    const int row = (int)(i / KDIM);
    float v = 0.f;
    if (row < OC_OFF)      v = wo[i];
    else if (row < OC_ALL) v = wm[i - (size_t)OC_OFF * KDIM];
    g_wpack[i] = tf32r(v);
}

// ---------------------------------------------------------------------------
// Stage I: im2col (tf32-rounded). block = 256 thr = 32 wo x 8 c, 16 c-chunks.
// g_cols[n][k], n = b*16384 + ho*128 + wo, k = c*9 + ky*3 + kx
// ---------------------------------------------------------------------------
__global__ __launch_bounds__(256)
void im2col_kernel(const float* __restrict__ x)
{
    __shared__ float st[32][73];
    const int t  = threadIdx.x;
    const int wl = t & 31;
    const int cl = t >> 5;
    const int n0 = blockIdx.x * 32;
    const int b  = n0 >> 14;
    const int ho = (n0 >> 7) & 127;
    const int wo = (n0 & 127) + wl;
    const int iy0 = 2 * ho - 1;
    const int ix0 = 2 * wo - 1;

    for (int cc = 0; cc < 16; ++cc) {
        const int c = cc * 8 + cl;
        const float* xp = x + (size_t)(b * C_ + c) * H_ * W_;
#pragma unroll
        for (int ky = 0; ky < 3; ++ky) {
            const int iy = iy0 + ky;
            const bool vy = (unsigned)iy < (unsigned)H_;
#pragma unroll
            for (int kx = 0; kx < 3; ++kx) {
                const int ix = ix0 + kx;
                float v = 0.f;
                if (vy && (unsigned)ix < (unsigned)W_) v = xp[iy * W_ + ix];
                st[wl][cl * 9 + ky * 3 + kx] = tf32r(v);
            }
        }
        __syncthreads();
        for (int i = t; i < 32 * 72; i += 256) {
            const int r = i / 72, col = i - r * 72;
            g_cols[(size_t)(n0 + r) * KDIM + cc * 72 + col] = st[r][col];
        }
        __syncthreads();
    }
}

// ---------------------------------------------------------------------------
// Stage G: tf32 mma.sync GEMM.
//   CTA tile 128(M) x 256(N), 512 thr = 16 warps, warp tile 32x64.
//   K chunk = 16 floats, 3-stage cp.async pipeline.
//   smem per stage: A[128][20] + B[256][20] (stride-20 pad, conflict-free).
// ---------------------------------------------------------------------------
#define MT      128
#define NT      256
#define KC      16
#define NKC     72          // 1152 / 16
#define NSTG    3
#define ASF     (MT * 20)   // floats per A stage
#define BSF     (NT * 20)
#define STGF    (ASF + BSF) // 7680 floats = 30720 B

__global__ __launch_bounds__(512, 1)
void gemm_tf32(const float* __restrict__ b_off, const float* __restrict__ b_msk)
{
    extern __shared__ float sm[];

    const int tid  = threadIdx.x;
    const int wid  = tid >> 5;
    const int lane = tid & 31;
    const int wm   = wid & 3;        // warp M tile (x32)
    const int wn   = wid >> 2;       // warp N tile (x64)
    const int lm   = lane >> 2;      // 0..7
    const int lk   = lane & 3;       // 0..3
    const int ocb  = blockIdx.x * MT;
    const int nb   = blockIdx.y * NT;

    const float* Abase = g_wpack + (size_t)ocb * KDIM;
    const float* Bbase = g_cols + (size_t)nb * KDIM;
    const uint32_t smb = smem_u32(sm);

    // producer indices (fixed per thread)
    const int ar = tid >> 2, ac = tid & 3;            // A: 1 chunk / thread

    float d[2][8][4];
#pragma unroll
    for (int t = 0; t < 2; ++t)
#pragma unroll
        for (int nt = 0; nt < 8; ++nt)
#pragma unroll
            for (int j = 0; j < 4; ++j) d[t][nt][j] = 0.f;

    // ---- prologue: load stages 0..NSTG-2 ----
#pragma unroll
    for (int s = 0; s < NSTG - 1; ++s) {
        const uint32_t stb = smb + s * STGF * 4;
        const float* As = Abase + s * KC;
        const float* Bs = Bbase + s * KC;
        CP_ASYNC16(stb + ar * 80 + ac * 16, As + (size_t)ar * KDIM + ac * 4);
#pragma unroll
        for (int j = 0; j < 2; ++j) {
            const int idx = tid + j * 512;
            const int br = idx >> 2, bc = idx & 3;
            CP_ASYNC16(stb + ASF * 4 + br * 80 + bc * 16,
                       Bs + (size_t)br * KDIM + bc * 4);
        }
        CP_COMMIT();
    }

    // ---- main loop ----
    for (int kc = 0; kc < NKC; ++kc) {
        if (kc < NKC - 2) { CP_WAIT(1); } else { CP_WAIT(0); }
        __syncthreads();

        const int slot = kc % NSTG;
        const float* Sa = sm + slot * STGF;
        const float* Sb = Sa + ASF;

#pragma unroll
        for (int ks = 0; ks < 2; ++ks) {
            const int k0 = ks * 8 + lk;
            float a[2][4];
#pragma unroll
            for (int t = 0; t < 2; ++t) {
                const float* pa = Sa + (wm * 32 + t * 16 + lm) * 20 + k0;
                a[t][0] = pa[0];
                a[t][1] = pa[8 * 20];
                a[t][2] = pa[4];
                a[t][3] = pa[8 * 20 + 4];
            }
            float bv[8][2];
#pragma unroll
            for (int nt = 0; nt < 8; ++nt) {
                const float* pb = Sb + (wn * 64 + nt * 8 + lm) * 20 + k0;
                bv[nt][0] = pb[0];
                bv[nt][1] = pb[4];
            }
#pragma unroll
            for (int t = 0; t < 2; ++t)
#pragma unroll
                for (int nt = 0; nt < 8; ++nt)
                    MMA_TF32(d[t][nt], a[t], bv[nt]);
        }
        __syncthreads();

        const int kn = kc + NSTG - 1;
        if (kn < NKC) {
            const uint32_t stb = smb + (kn % NSTG) * STGF * 4;
            const float* As = Abase + kn * KC;
            const float* Bs = Bbase + kn * KC;
            CP_ASYNC16(stb + ar * 80 + ac * 16, As + (size_t)ar * KDIM + ac * 4);
#pragma unroll
            for (int j = 0; j < 2; ++j) {
                const int idx = tid + j * 512;
                const int br = idx >> 2, bc = idx & 3;
                CP_ASYNC16(stb + ASF * 4 + br * 80 + bc * 16,
                           Bs + (size_t)br * KDIM + bc * 4);
            }
            CP_COMMIT();
        }
    }

    // ---- epilogue: bias (+sigmoid), float2 coalesced stores ----
    const int b    = nb >> 14;
    const int pixb = nb & 16383;

#pragma unroll
    for (int t = 0; t < 2; ++t) {
        const int r0 = ocb + wm * 32 + t * 16 + lm;   // rows r0 and r0+8
#pragma unroll
        for (int half = 0; half < 2; ++half) {
            const int oc = r0 + half * 8;
            if (oc >= OC_ALL) continue;
            const bool msk = (oc >= OC_OFF);
            const float bias = msk ? b_msk[oc - OC_OFF] : b_off[oc];
            float* rowp = g_conv + ((size_t)b * OC_ALL + oc) * 16384 + pixb;
#pragma unroll
            for (int nt = 0; nt < 8; ++nt) {
                const int col = wn * 64 + nt * 8 + 2 * lk;
                float v0 = d[t][nt][2 * half + 0] + bias;
                float v1 = d[t][nt][2 * half + 1] + bias;
                if (msk) {
                    v0 = 1.f / (1.f + __expf(-v0));
                    v1 = 1.f / (1.f + __expf(-v1));
                }
                *reinterpret_cast<float2*>(rowp + col) = make_float2(v0, v1);
            }
        }
    }
}

// ---------------------------------------------------------------------------
// Stage D: modulated deformable gather + per-group 2x2x9 matmul
// ---------------------------------------------------------------------------
__global__ __launch_bounds__(128)
void deform_kernel(const float* __restrict__ x,
                   const float* __restrict__ w_deform,
                   float* __restrict__ out)
{
    const int blk = blockIdx.x;
    const int ho  = blk & 127;
    const int g   = (blk >> 7) & 63;
    const int b   = blk >> 13;
    const int wo  = threadIdx.x;

    __shared__ float wd[2][2][9];
    if (threadIdx.x < 36) {
        const int o = threadIdx.x / 18;
        const int c = (threadIdx.x / 9) & 1;
        const int k = threadIdx.x % 9;
        wd[o][c][k] = w_deform[(((size_t)(g * 2 + o)) * 2 + c) * 9 + k];
    }
    __syncthreads();

    const float* xg0 = x + ((size_t)(b * C_ + g * 2) * H_) * W_;
    const float* xg1 = xg0 + (size_t)H_ * W_;

    const size_t CS  = (size_t)HO_ * WO_;
    const size_t pix = (size_t)ho * WO_ + wo;
    const float* cv_b = g_conv + (size_t)b * OC_ALL * CS + pix;

    float acc0 = 0.f, acc1 = 0.f;

#pragma unroll
    for (int k = 0; k < 9; ++k) {
        const int choff = (g * 9 + k) * 2;
        const float dy = cv_b[(size_t)choff * CS];
        const float dx = cv_b[(size_t)(choff + 1) * CS];
        const float m  = cv_b[(size_t)(OC_OFF + g * 9 + k) * CS];

        const int ki = k / 3, kj = k - ki * 3;
        const float py = dy + (float)(2 * ho - 1 + ki);
        const float px = dx + (float)(2 * wo - 1 + kj);

        const float y0f = floorf(py), x0f = floorf(px);
        const float wy = py - y0f, wx = px - x0f;
        const int y0 = (int)y0f, x0 = (int)x0f;
        const int y1 = y0 + 1, x1 = x0 + 1;

        const bool vy0 = (unsigned)y0 < (unsigned)H_;
        const bool vy1 = (unsigned)y1 < (unsigned)H_;
        const bool vx0 = (unsigned)x0 < (unsigned)W_;
        const bool vx1 = (unsigned)x1 < (unsigned)W_;

        const float w00 = (1.f - wy) * (1.f - wx);
        const float w01 = (1.f - wy) * wx;
        const float w10 = wy * (1.f - wx);
        const float w11 = wy * wx;

        const int i00 = y0 * W_ + x0;
        const int i01 = y0 * W_ + x1;
        const int i10 = y1 * W_ + x0;
        const int i11 = y1 * W_ + x1;

        float s0 = 0.f, s1 = 0.f;
        if (vy0 && vx0) { s0 += w00 * xg0[i00]; s1 += w00 * xg1[i00]; }
        if (vy0 && vx1) { s0 += w01 * xg0[i01]; s1 += w01 * xg1[i01]; }
        if (vy1 && vx0) { s0 += w10 * xg0[i10]; s1 += w10 * xg1[i10]; }
        if (vy1 && vx1) { s0 += w11 * xg0[i11]; s1 += w11 * xg1[i11]; }

        s0 *= m; s1 *= m;
        acc0 = fmaf(s0, wd[0][0][k], acc0);
        acc0 = fmaf(s1, wd[0][1][k], acc0);
        acc1 = fmaf(s0, wd[1][0][k], acc1);
        acc1 = fmaf(s1, wd[1][1][k], acc1);
    }

    float* o0 = out + (((size_t)b * C_ + g * 2) * HO_ + ho) * WO_ + wo;
    o0[0]  = acc0;
    o0[CS] = acc1;
}

// ---------------------------------------------------------------------------
extern "C" void kernel_launch(void* const* d_in, const int* in_sizes, int n_in,
                              void* d_out, int out_size)
{
    const float* x        = (const float*)d_in[0];
    const float* w_offset = (const float*)d_in[1];
    const float* b_offset = (const float*)d_in[2];
    const float* w_mask   = (const float*)d_in[3];
    const float* b_mask   = (const float*)d_in[4];
    const float* w_deform = (const float*)d_in[5];
    float* out = (float*)d_out;

    // Stage P: pack + tf32-round weights
    const size_t wtot = (size_t)MPAD * KDIM;
    pack_w<<<(unsigned)((wtot + 255) / 256), 256>>>(w_offset, w_mask);

    // Stage I: im2col (tf32-rounded)
    im2col_kernel<<<NPIX / 32, 256>>>(x);

    // Stage G: tf32 mma.sync GEMM + fused bias/sigmoid
    const int smem = NSTG * STGF * (int)sizeof(float);   // 92160 B
    cudaFuncSetAttribute(gemm_tf32, cudaFuncAttributeMaxDynamicSharedMemorySize, smem);
    gemm_tf32<<<dim3(MPAD / MT, NPIX / NT), 512, smem>>>(b_offset, b_mask);

    // Stage D: deformable gather + group matmul
    deform_kernel<<<B_ * G_ * HO_, 128>>>(x, w_deform, out);
}

// round 4
// speedup vs baseline: 5.3511x; 1.1913x over previous
#include <cuda_runtime.h>
#include <cstdint>

// ---------------------------------------------------------------------------
// DCNv2 on GB300 (compute_103 PTX target -> no tcgen05; use mma.sync tf32):
//   Stage P: pack weights -> g_wpack [1792, 1152], tf32-rounded
//   Stage I: im2col x -> g_cols [32768, 1152], tf32-rounded
//   Stage G: mma.sync.m16n8k8 tf32 GEMM D[1728, 32768] = W x cols,
//            fused bias/sigmoid, -> g_conv[b][oc][pix]
//   Stage D: bilinear deformable gather + per-group 2x2x9 matmul
// ---------------------------------------------------------------------------

#define B_      2
#define C_      128
#define H_      256
#define W_      256
#define HO_     128
#define WO_     128
#define G_      64
#define OC_OFF  1152
#define OC_ALL  1728
#define KDIM    1152
#define NPIX    32768
#define MPAD    1792

__device__ __align__(1024) float g_conv[(size_t)B_ * OC_ALL * HO_ * WO_];
__device__ __align__(1024) float g_cols[(size_t)NPIX * KDIM];
__device__ __align__(1024) float g_wpack[(size_t)MPAD * KDIM];

// ------------------------------- helpers ----------------------------------
__device__ __forceinline__ float tf32r(float v) {
    uint32_t o;
    asm("cvt.rna.tf32.f32 %0, %1;" : "=r"(o) : "f"(v));
    return __uint_as_float(o);
}
__device__ __forceinline__ uint32_t smem_u32(const void* p) {
    uint32_t a;
    asm("{ .reg .u64 t; cvta.to.shared.u64 t, %1; cvt.u32.u64 %0, t; }" : "=r"(a) : "l"(p));
    return a;
}
#define CP_ASYNC16(dst, src) \
    asm volatile("cp.async.cg.shared.global [%0], [%1], 16;" :: "r"(dst), "l"(src) : "memory")
#define CP_COMMIT() asm volatile("cp.async.commit_group;" ::: "memory")
#define CP_WAIT(n)  asm volatile("cp.async.wait_group %0;" :: "n"(n) : "memory")

#define MMA_TF32(d, a, b)                                                      \
    asm volatile("mma.sync.aligned.m16n8k8.row.col.f32.tf32.tf32.f32 "         \
        "{%0,%1,%2,%3}, {%4,%5,%6,%7}, {%8,%9}, {%0,%1,%2,%3};"                \
        : "+f"((d)[0]), "+f"((d)[1]), "+f"((d)[2]), "+f"((d)[3])               \
        : "r"(__float_as_uint((a)[0])), "r"(__float_as_uint((a)[1])),          \
          "r"(__float_as_uint((a)[2])), "r"(__float_as_uint((a)[3])),          \
          "r"(__float_as_uint((b)[0])), "r"(__float_as_uint((b)[1])))

// ---------------------------------------------------------------------------
// Stage P: pack + tf32-round weights. rows >= 1728 zero.
// ---------------------------------------------------------------------------
__global__ __launch_bounds__(256)
void pack_w(const float* __restrict__ wo, const float* __restrict__ wm)
{
    const size_t i = (size_t)blockIdx.x * 256 + threadIdx.x;
    if (i >= (size_t)MPAD * KDIM) return;
    const int row = (int)(i / KDIM);
    float v = 0.f;
    if (row < OC_OFF)      v = wo[i];
    else if (row < OC_ALL) v = wm[i - (size_t)OC_OFF * KDIM];
    g_wpack[i] = tf32r(v);
}

// ---------------------------------------------------------------------------
// Stage I: im2col (tf32-rounded). block = 256 thr = 32 wo x 8 c, 16 c-chunks.
// ---------------------------------------------------------------------------
__global__ __launch_bounds__(256)
void im2col_kernel(const float* __restrict__ x)
{
    __shared__ float st[32][73];
    const int t  = threadIdx.x;
    const int wl = t & 31;
    const int cl = t >> 5;
    const int n0 = blockIdx.x * 32;
    const int b  = n0 >> 14;
    const int ho = (n0 >> 7) & 127;
    const int wo = (n0 & 127) + wl;
    const int iy0 = 2 * ho - 1;
    const int ix0 = 2 * wo - 1;

    for (int cc = 0; cc < 16; ++cc) {
        const int c = cc * 8 + cl;
        const float* xp = x + (size_t)(b * C_ + c) * H_ * W_;
#pragma unroll
        for (int ky = 0; ky < 3; ++ky) {
            const int iy = iy0 + ky;
            const bool vy = (unsigned)iy < (unsigned)H_;
#pragma unroll
            for (int kx = 0; kx < 3; ++kx) {
                const int ix = ix0 + kx;
                float v = 0.f;
                if (vy && (unsigned)ix < (unsigned)W_) v = xp[iy * W_ + ix];
                st[wl][cl * 9 + ky * 3 + kx] = tf32r(v);
            }
        }
        __syncthreads();
        for (int i = t; i < 32 * 72; i += 256) {
            const int r = i / 72, col = i - r * 72;
            g_cols[(size_t)(n0 + r) * KDIM + cc * 72 + col] = st[r][col];
        }
        __syncthreads();
    }
}

// ---------------------------------------------------------------------------
// Stage G: tf32 mma.sync GEMM.
//   CTA tile 128(M) x 256(N), 512 thr = 16 warps, warp tile 32x64.
//   K chunk = 32 floats, 3-stage cp.async pipeline, ONE syncthreads/iter,
//   loads for stage kc+2 issued before compute of stage kc.
//   smem per stage: A[128][36] + B[256][36] (stride-36 pad, conflict-free).
// ---------------------------------------------------------------------------
#define MT      128
#define NT      256
#define KC      32
#define NKC     36          // 1152 / 32
#define NSTG    3
#define LDP     36          // row stride in floats
#define ASF     (MT * LDP)  // 4608 floats / A stage
#define BSF     (NT * LDP)  // 9216 floats / B stage
#define STGF    (ASF + BSF) // 13824 floats = 55296 B

__global__ __launch_bounds__(512, 1)
void gemm_tf32(const float* __restrict__ b_off, const float* __restrict__ b_msk)
{
    extern __shared__ float sm[];

    const int tid  = threadIdx.x;
    const int wid  = tid >> 5;
    const int lane = tid & 31;
    const int wm   = wid & 3;        // warp M tile (x32)
    const int wn   = wid >> 2;       // warp N tile (x64)
    const int lm   = lane >> 2;      // 0..7
    const int lk   = lane & 3;       // 0..3
    const int ocb  = blockIdx.x * MT;
    const int nb   = blockIdx.y * NT;

    const float* Abase = g_wpack + (size_t)ocb * KDIM;
    const float* Bbase = g_cols + (size_t)nb * KDIM;
    const uint32_t smb = smem_u32(sm);

    float d[2][8][4];
#pragma unroll
    for (int t = 0; t < 2; ++t)
#pragma unroll
        for (int nt = 0; nt < 8; ++nt)
#pragma unroll
            for (int j = 0; j < 4; ++j) d[t][nt][j] = 0.f;

    // ---- one stage load: A 128x128B (1024 x 16B), B 256x128B (2048 x 16B) --
    auto load_stage = [&](int kn) {
        const uint32_t stb = smb + (kn % NSTG) * STGF * 4;
        const float* As = Abase + kn * KC;
        const float* Bs = Bbase + kn * KC;
#pragma unroll
        for (int j = 0; j < 2; ++j) {
            const int i = tid + j * 512;
            const int r = i >> 3, c = i & 7;
            CP_ASYNC16(stb + (uint32_t)(r * LDP + c * 4) * 4,
                       As + (size_t)r * KDIM + c * 4);
        }
#pragma unroll
        for (int j = 0; j < 4; ++j) {
            const int i = tid + j * 512;
            const int r = i >> 3, c = i & 7;
            CP_ASYNC16(stb + (uint32_t)(ASF + r * LDP + c * 4) * 4,
                       Bs + (size_t)r * KDIM + c * 4);
        }
        CP_COMMIT();
    };

    // ---- prologue: stages 0, 1 ----
    load_stage(0);
    load_stage(1);

    // ---- main loop: one sync per iter, loads issued before compute ----
    for (int kc = 0; kc < NKC; ++kc) {
        CP_WAIT(1);
        __syncthreads();

        if (kc + 2 < NKC) load_stage(kc + 2);   // slot (kc+2)%3 freed at this barrier

        const float* Sa = sm + (kc % NSTG) * STGF;
        const float* Sb = Sa + ASF;

#pragma unroll
        for (int ks = 0; ks < 4; ++ks) {
            const int k0 = ks * 8 + lk;
            float a[2][4];
#pragma unroll
            for (int t = 0; t < 2; ++t) {
                const float* pa = Sa + (wm * 32 + t * 16 + lm) * LDP + k0;
                a[t][0] = pa[0];
                a[t][1] = pa[8 * LDP];
                a[t][2] = pa[4];
                a[t][3] = pa[8 * LDP + 4];
            }
            float bv[8][2];
#pragma unroll
            for (int nt = 0; nt < 8; ++nt) {
                const float* pb = Sb + (wn * 64 + nt * 8 + lm) * LDP + k0;
                bv[nt][0] = pb[0];
                bv[nt][1] = pb[4];
            }
#pragma unroll
            for (int t = 0; t < 2; ++t)
#pragma unroll
                for (int nt = 0; nt < 8; ++nt)
                    MMA_TF32(d[t][nt], a[t], bv[nt]);
        }
    }

    // ---- epilogue: bias (+sigmoid), float2 coalesced stores ----
    const int b    = nb >> 14;
    const int pixb = nb & 16383;

#pragma unroll
    for (int t = 0; t < 2; ++t) {
        const int r0 = ocb + wm * 32 + t * 16 + lm;   // rows r0 and r0+8
#pragma unroll
        for (int half = 0; half < 2; ++half) {
            const int oc = r0 + half * 8;
            if (oc >= OC_ALL) continue;
            const bool msk = (oc >= OC_OFF);
            const float bias = msk ? b_msk[oc - OC_OFF] : b_off[oc];
            float* rowp = g_conv + ((size_t)b * OC_ALL + oc) * 16384 + pixb;
#pragma unroll
            for (int nt = 0; nt < 8; ++nt) {
                const int col = wn * 64 + nt * 8 + 2 * lk;
                float v0 = d[t][nt][2 * half + 0] + bias;
                float v1 = d[t][nt][2 * half + 1] + bias;
                if (msk) {
                    v0 = 1.f / (1.f + __expf(-v0));
                    v1 = 1.f / (1.f + __expf(-v1));
                }
                *reinterpret_cast<float2*>(rowp + col) = make_float2(v0, v1);
            }
        }
    }
}

// ---------------------------------------------------------------------------
// Stage D: modulated deformable gather + per-group 2x2x9 matmul
// ---------------------------------------------------------------------------
__global__ __launch_bounds__(128)
void deform_kernel(const float* __restrict__ x,
                   const float* __restrict__ w_deform,
                   float* __restrict__ out)
{
    const int blk = blockIdx.x;
    const int ho  = blk & 127;
    const int g   = (blk >> 7) & 63;
    const int b   = blk >> 13;
    const int wo  = threadIdx.x;

    __shared__ float wd[2][2][9];
    if (threadIdx.x < 36) {
        const int o = threadIdx.x / 18;
        const int c = (threadIdx.x / 9) & 1;
        const int k = threadIdx.x % 9;
        wd[o][c][k] = w_deform[(((size_t)(g * 2 + o)) * 2 + c) * 9 + k];
    }
    __syncthreads();

    const float* xg0 = x + ((size_t)(b * C_ + g * 2) * H_) * W_;
    const float* xg1 = xg0 + (size_t)H_ * W_;

    const size_t CS  = (size_t)HO_ * WO_;
    const size_t pix = (size_t)ho * WO_ + wo;
    const float* cv_b = g_conv + (size_t)b * OC_ALL * CS + pix;

    float acc0 = 0.f, acc1 = 0.f;

#pragma unroll
    for (int k = 0; k < 9; ++k) {
        const int choff = (g * 9 + k) * 2;
        const float dy = cv_b[(size_t)choff * CS];
        const float dx = cv_b[(size_t)(choff + 1) * CS];
        const float m  = cv_b[(size_t)(OC_OFF + g * 9 + k) * CS];

        const int ki = k / 3, kj = k - ki * 3;
        const float py = dy + (float)(2 * ho - 1 + ki);
        const float px = dx + (float)(2 * wo - 1 + kj);

        const float y0f = floorf(py), x0f = floorf(px);
        const float wy = py - y0f, wx = px - x0f;
        const int y0 = (int)y0f, x0 = (int)x0f;
        const int y1 = y0 + 1, x1 = x0 + 1;

        const bool vy0 = (unsigned)y0 < (unsigned)H_;
        const bool vy1 = (unsigned)y1 < (unsigned)H_;
        const bool vx0 = (unsigned)x0 < (unsigned)W_;
        const bool vx1 = (unsigned)x1 < (unsigned)W_;

        const float w00 = (1.f - wy) * (1.f - wx);
        const float w01 = (1.f - wy) * wx;
        const float w10 = wy * (1.f - wx);
        const float w11 = wy * wx;

        const int i00 = y0 * W_ + x0;
        const int i01 = y0 * W_ + x1;
        const int i10 = y1 * W_ + x0;
        const int i11 = y1 * W_ + x1;

        float s0 = 0.f, s1 = 0.f;
        if (vy0 && vx0) { s0 += w00 * xg0[i00]; s1 += w00 * xg1[i00]; }
        if (vy0 && vx1) { s0 += w01 * xg0[i01]; s1 += w01 * xg1[i01]; }
        if (vy1 && vx0) { s0 += w10 * xg0[i10]; s1 += w10 * xg1[i10]; }
        if (vy1 && vx1) { s0 += w11 * xg0[i11]; s1 += w11 * xg1[i11]; }

        s0 *= m; s1 *= m;
        acc0 = fmaf(s0, wd[0][0][k], acc0);
        acc0 = fmaf(s1, wd[0][1][k], acc0);
        acc1 = fmaf(s0, wd[1][0][k], acc1);
        acc1 = fmaf(s1, wd[1][1][k], acc1);
    }

    float* o0 = out + (((size_t)b * C_ + g * 2) * HO_ + ho) * WO_ + wo;
    o0[0]  = acc0;
    o0[CS] = acc1;
}

// ---------------------------------------------------------------------------
extern "C" void kernel_launch(void* const* d_in, const int* in_sizes, int n_in,
                              void* d_out, int out_size)
{
    const float* x        = (const float*)d_in[0];
    const float* w_offset = (const float*)d_in[1];
    const float* b_offset = (const float*)d_in[2];
    const float* w_mask   = (const float*)d_in[3];
    const float* b_mask   = (const float*)d_in[4];
    const float* w_deform = (const float*)d_in[5];
    float* out = (float*)d_out;

    // Stage P: pack + tf32-round weights
    const size_t wtot = (size_t)MPAD * KDIM;
    pack_w<<<(unsigned)((wtot + 255) / 256), 256>>>(w_offset, w_mask);

    // Stage I: im2col (tf32-rounded)
    im2col_kernel<<<NPIX / 32, 256>>>(x);

    // Stage G: tf32 mma.sync GEMM + fused bias/sigmoid
    const int smem = NSTG * STGF * (int)sizeof(float);   // 165888 B
    cudaFuncSetAttribute(gemm_tf32, cudaFuncAttributeMaxDynamicSharedMemorySize, smem);
    gemm_tf32<<<dim3(MPAD / MT, NPIX / NT), 512, smem>>>(b_offset, b_mask);

    // Stage D: deformable gather + group matmul
    deform_kernel<<<B_ * G_ * HO_, 128>>>(x, w_deform, out);
}

// round 5
// speedup vs baseline: 9.9905x; 1.8670x over previous
#include <cuda_runtime.h>
#include <cuda_fp16.h>
#include <cstdint>

// ---------------------------------------------------------------------------
// DCNv2 on GB300 (compute_103 PTX -> no tcgen05; use fp16 mma.sync m16n8k16):
//   Stage P: pack weights -> g_wpack [1792, 1152] fp16
//   Stage I: im2col x -> g_cols [32768, 1152] fp16
//   Stage G: fp16 mma.sync GEMM D[1728, 32768] = W x cols (fp32 accum),
//            fused bias/sigmoid, -> g_conv[b][oc][pix]
//   Stage D: bilinear deformable gather + per-group 2x2x9 matmul
// ---------------------------------------------------------------------------

#define B_      2
#define C_      128
#define H_      256
#define W_      256
#define HO_     128
#define WO_     128
#define G_      64
#define OC_OFF  1152
#define OC_ALL  1728
#define KDIM    1152
#define NPIX    32768
#define MPAD    1792

__device__ __align__(1024) float  g_conv[(size_t)B_ * OC_ALL * HO_ * WO_];
__device__ __align__(1024) __half g_cols[(size_t)NPIX * KDIM];
__device__ __align__(1024) __half g_wpack[(size_t)MPAD * KDIM];

// ------------------------------- helpers ----------------------------------
__device__ __forceinline__ uint32_t smem_u32(const void* p) {
    uint32_t a;
    asm("{ .reg .u64 t; cvta.to.shared.u64 t, %1; cvt.u32.u64 %0, t; }" : "=r"(a) : "l"(p));
    return a;
}
#define CP_ASYNC16(dst, src) \
    asm volatile("cp.async.cg.shared.global [%0], [%1], 16;" :: "r"(dst), "l"(src) : "memory")
#define CP_COMMIT() asm volatile("cp.async.commit_group;" ::: "memory")
#define CP_WAIT(n)  asm volatile("cp.async.wait_group %0;" :: "n"(n) : "memory")

#define LDSM_X4(r0, r1, r2, r3, addr)                                          \
    asm volatile("ldmatrix.sync.aligned.m8n8.x4.shared.b16 {%0,%1,%2,%3}, [%4];" \
        : "=r"(r0), "=r"(r1), "=r"(r2), "=r"(r3) : "r"(addr))

#define MMA_F16(d, a, b)                                                       \
    asm volatile("mma.sync.aligned.m16n8k16.row.col.f32.f16.f16.f32 "          \
        "{%0,%1,%2,%3}, {%4,%5,%6,%7}, {%8,%9}, {%0,%1,%2,%3};"                \
        : "+f"((d)[0]), "+f"((d)[1]), "+f"((d)[2]), "+f"((d)[3])               \
        : "r"((a)[0]), "r"((a)[1]), "r"((a)[2]), "r"((a)[3]),                  \
          "r"((b)[0]), "r"((b)[1]))

// ---------------------------------------------------------------------------
// Stage P: pack weights -> fp16. rows >= 1728 zero.
// ---------------------------------------------------------------------------
__global__ __launch_bounds__(256)
void pack_w(const float* __restrict__ wo, const float* __restrict__ wm)
{
    const size_t i = (size_t)blockIdx.x * 256 + threadIdx.x;
    if (i >= (size_t)MPAD * KDIM) return;
    const int row = (int)(i / KDIM);
    float v = 0.f;
    if (row < OC_OFF)      v = wo[i];
    else if (row < OC_ALL) v = wm[i - (size_t)OC_OFF * KDIM];
    g_wpack[i] = __float2half_rn(v);
}

// ---------------------------------------------------------------------------
// Stage I: im2col -> fp16. block = 256 thr = 32 wo x 8 c, 16 c-chunks.
// g_cols[n][k], n = b*16384 + ho*128 + wo, k = c*9 + ky*3 + kx
// ---------------------------------------------------------------------------
__global__ __launch_bounds__(256)
void im2col_kernel(const float* __restrict__ x)
{
    __shared__ float st[32][73];
    const int t  = threadIdx.x;
    const int wl = t & 31;
    const int cl = t >> 5;
    const int n0 = blockIdx.x * 32;
    const int b  = n0 >> 14;
    const int ho = (n0 >> 7) & 127;
    const int wo = (n0 & 127) + wl;
    const int iy0 = 2 * ho - 1;
    const int ix0 = 2 * wo - 1;

    for (int cc = 0; cc < 16; ++cc) {
        const int c = cc * 8 + cl;
        const float* xp = x + (size_t)(b * C_ + c) * H_ * W_;
#pragma unroll
        for (int ky = 0; ky < 3; ++ky) {
            const int iy = iy0 + ky;
            const bool vy = (unsigned)iy < (unsigned)H_;
#pragma unroll
            for (int kx = 0; kx < 3; ++kx) {
                const int ix = ix0 + kx;
                float v = 0.f;
                if (vy && (unsigned)ix < (unsigned)W_) v = xp[iy * W_ + ix];
                st[wl][cl * 9 + ky * 3 + kx] = v;
            }
        }
        __syncthreads();
        for (int i = t; i < 32 * 72; i += 256) {
            const int r = i / 72, col = i - r * 72;
            g_cols[(size_t)(n0 + r) * KDIM + cc * 72 + col] = __float2half_rn(st[r][col]);
        }
        __syncthreads();
    }
}

// ---------------------------------------------------------------------------
// Stage G: fp16 mma.sync GEMM.
//   CTA tile 128(M) x 256(N), 512 thr = 16 warps, warp tile 32x64.
//   K chunk = 64 halfs (4 k16 steps), 3-stage cp.async pipeline,
//   one syncthreads/iter, ldmatrix fragment loads.
//   smem per stage: A[128][72] + B[256][72] halfs (stride-72 pad).
// ---------------------------------------------------------------------------
#define MT      128
#define NT      256
#define KCH     64
#define NKC     18          // 1152 / 64
#define NSTG    3
#define LDP     72          // row stride in halfs
#define ASF     (MT * LDP)  // 9216 halfs / A stage
#define BSF     (NT * LDP)  // 18432 halfs / B stage
#define STGH    (ASF + BSF) // 27648 halfs = 55296 B
#define STGB    (STGH * 2)

__global__ __launch_bounds__(512, 1)
void gemm_f16(const float* __restrict__ b_off, const float* __restrict__ b_msk)
{
    extern __shared__ __half sm[];

    const int tid  = threadIdx.x;
    const int wid  = tid >> 5;
    const int lane = tid & 31;
    const int wm   = wid & 3;        // warp M tile (x32)
    const int wn   = wid >> 2;       // warp N tile (x64)
    const int lm   = lane >> 2;      // 0..7 (D fragment row)
    const int lk   = lane & 3;       // 0..3 (D fragment col pair)
    const int g    = lane >> 3;      // ldmatrix lane group 0..3
    const int li   = lane & 7;       // row within group
    const int ocb  = blockIdx.x * MT;
    const int nb   = blockIdx.y * NT;

    const __half* Abase = g_wpack + (size_t)ocb * KDIM;
    const __half* Bbase = g_cols + (size_t)nb * KDIM;
    const uint32_t smb = smem_u32(sm);

    // per-lane ldmatrix byte offsets within a stage
    // A: group g -> row += (g&1)*8, col += (g>>1)*8
    const uint32_t aoff = (uint32_t)((wm * 32 + (g & 1) * 8 + li) * LDP + (g >> 1) * 8) * 2;
    // B: group g -> row(n) += (g>>1)*8, col(k) += (g&1)*8
    const uint32_t boff = (uint32_t)(ASF + (wn * 64 + (g >> 1) * 8 + li) * LDP + (g & 1) * 8) * 2;

    float d[2][8][4];
#pragma unroll
    for (int t = 0; t < 2; ++t)
#pragma unroll
        for (int nt = 0; nt < 8; ++nt)
#pragma unroll
            for (int j = 0; j < 4; ++j) d[t][nt][j] = 0.f;

    // ---- one stage: A 128x128B (1024x16B), B 256x128B (2048x16B) ----
    auto load_stage = [&](int kn) {
        const uint32_t stb = smb + (uint32_t)(kn % NSTG) * STGB;
        const __half* As = Abase + kn * KCH;
        const __half* Bs = Bbase + kn * KCH;
#pragma unroll
        for (int j = 0; j < 2; ++j) {
            const int i = tid + j * 512;
            const int r = i >> 3, c = i & 7;
            CP_ASYNC16(stb + (uint32_t)(r * LDP + c * 8) * 2,
                       As + (size_t)r * KDIM + c * 8);
        }
#pragma unroll
        for (int j = 0; j < 4; ++j) {
            const int i = tid + j * 512;
            const int r = i >> 3, c = i & 7;
            CP_ASYNC16(stb + (uint32_t)(ASF + r * LDP + c * 8) * 2,
                       Bs + (size_t)r * KDIM + c * 8);
        }
        CP_COMMIT();
    };

    load_stage(0);
    load_stage(1);

    for (int kc = 0; kc < NKC; ++kc) {
        CP_WAIT(1);
        __syncthreads();

        if (kc + 2 < NKC) load_stage(kc + 2);

        const uint32_t sb = smb + (uint32_t)(kc % NSTG) * STGB;

#pragma unroll
        for (int ks = 0; ks < 4; ++ks) {
            const uint32_t kb = (uint32_t)ks * 32;       // 16 halfs
            uint32_t a[2][4];
            LDSM_X4(a[0][0], a[0][1], a[0][2], a[0][3], sb + aoff + kb);
            LDSM_X4(a[1][0], a[1][1], a[1][2], a[1][3],
                    sb + aoff + 16 * LDP * 2 + kb);
            uint32_t bw[8][2];
#pragma unroll
            for (int np = 0; np < 4; ++np)
                LDSM_X4(bw[np * 2][0], bw[np * 2][1],
                        bw[np * 2 + 1][0], bw[np * 2 + 1][1],
                        sb + boff + (uint32_t)(np * 16 * LDP) * 2 + kb);
#pragma unroll
            for (int t = 0; t < 2; ++t)
#pragma unroll
                for (int nt = 0; nt < 8; ++nt)
                    MMA_F16(d[t][nt], a[t], bw[nt]);
        }
    }

    // ---- epilogue: bias (+sigmoid), float2 coalesced stores ----
    const int b    = nb >> 14;
    const int pixb = nb & 16383;

#pragma unroll
    for (int t = 0; t < 2; ++t) {
        const int r0 = ocb + wm * 32 + t * 16 + lm;
#pragma unroll
        for (int half = 0; half < 2; ++half) {
            const int oc = r0 + half * 8;
            if (oc >= OC_ALL) continue;
            const bool msk = (oc >= OC_OFF);
            const float bias = msk ? b_msk[oc - OC_OFF] : b_off[oc];
            float* rowp = g_conv + ((size_t)b * OC_ALL + oc) * 16384 + pixb;
#pragma unroll
            for (int nt = 0; nt < 8; ++nt) {
                const int col = wn * 64 + nt * 8 + 2 * lk;
                float v0 = d[t][nt][2 * half + 0] + bias;
                float v1 = d[t][nt][2 * half + 1] + bias;
                if (msk) {
                    v0 = 1.f / (1.f + __expf(-v0));
                    v1 = 1.f / (1.f + __expf(-v1));
                }
                *reinterpret_cast<float2*>(rowp + col) = make_float2(v0, v1);
            }
        }
    }
}

// ---------------------------------------------------------------------------
// Stage D: modulated deformable gather + per-group 2x2x9 matmul
// ---------------------------------------------------------------------------
__global__ __launch_bounds__(128)
void deform_kernel(const float* __restrict__ x,
                   const float* __restrict__ w_deform,
                   float* __restrict__ out)
{
    const int blk = blockIdx.x;
    const int ho  = blk & 127;
    const int g   = (blk >> 7) & 63;
    const int b   = blk >> 13;
    const int wo  = threadIdx.x;

    __shared__ float wd[2][2][9];
    if (threadIdx.x < 36) {
        const int o = threadIdx.x / 18;
        const int c = (threadIdx.x / 9) & 1;
        const int k = threadIdx.x % 9;
        wd[o][c][k] = w_deform[(((size_t)(g * 2 + o)) * 2 + c) * 9 + k];
    }
    __syncthreads();

    const float* xg0 = x + ((size_t)(b * C_ + g * 2) * H_) * W_;
    const float* xg1 = xg0 + (size_t)H_ * W_;

    const size_t CS  = (size_t)HO_ * WO_;
    const size_t pix = (size_t)ho * WO_ + wo;
    const float* cv_b = g_conv + (size_t)b * OC_ALL * CS + pix;

    float acc0 = 0.f, acc1 = 0.f;

#pragma unroll
    for (int k = 0; k < 9; ++k) {
        const int choff = (g * 9 + k) * 2;
        const float dy = cv_b[(size_t)choff * CS];
        const float dx = cv_b[(size_t)(choff + 1) * CS];
        const float m  = cv_b[(size_t)(OC_OFF + g * 9 + k) * CS];

        const int ki = k / 3, kj = k - ki * 3;
        const float py = dy + (float)(2 * ho - 1 + ki);
        const float px = dx + (float)(2 * wo - 1 + kj);

        const float y0f = floorf(py), x0f = floorf(px);
        const float wy = py - y0f, wx = px - x0f;
        const int y0 = (int)y0f, x0 = (int)x0f;
        const int y1 = y0 + 1, x1 = x0 + 1;

        const bool vy0 = (unsigned)y0 < (unsigned)H_;
        const bool vy1 = (unsigned)y1 < (unsigned)H_;
        const bool vx0 = (unsigned)x0 < (unsigned)W_;
        const bool vx1 = (unsigned)x1 < (unsigned)W_;

        const float w00 = (1.f - wy) * (1.f - wx);
        const float w01 = (1.f - wy) * wx;
        const float w10 = wy * (1.f - wx);
        const float w11 = wy * wx;

        const int i00 = y0 * W_ + x0;
        const int i01 = y0 * W_ + x1;
        const int i10 = y1 * W_ + x0;
        const int i11 = y1 * W_ + x1;

        float s0 = 0.f, s1 = 0.f;
        if (vy0 && vx0) { s0 += w00 * xg0[i00]; s1 += w00 * xg1[i00]; }
        if (vy0 && vx1) { s0 += w01 * xg0[i01]; s1 += w01 * xg1[i01]; }
        if (vy1 && vx0) { s0 += w10 * xg0[i10]; s1 += w10 * xg1[i10]; }
        if (vy1 && vx1) { s0 += w11 * xg0[i11]; s1 += w11 * xg1[i11]; }

        s0 *= m; s1 *= m;
        acc0 = fmaf(s0, wd[0][0][k], acc0);
        acc0 = fmaf(s1, wd[0][1][k], acc0);
        acc1 = fmaf(s0, wd[1][0][k], acc1);
        acc1 = fmaf(s1, wd[1][1][k], acc1);
    }

    float* o0 = out + (((size_t)b * C_ + g * 2) * HO_ + ho) * WO_ + wo;
    o0[0]  = acc0;
    o0[CS] = acc1;
}

// ---------------------------------------------------------------------------
extern "C" void kernel_launch(void* const* d_in, const int* in_sizes, int n_in,
                              void* d_out, int out_size)
{
    const float* x        = (const float*)d_in[0];
    const float* w_offset = (const float*)d_in[1];
    const float* b_offset = (const float*)d_in[2];
    const float* w_mask   = (const float*)d_in[3];
    const float* b_mask   = (const float*)d_in[4];
    const float* w_deform = (const float*)d_in[5];
    float* out = (float*)d_out;

    // Stage P: pack weights -> fp16
    const size_t wtot = (size_t)MPAD * KDIM;
    pack_w<<<(unsigned)((wtot + 255) / 256), 256>>>(w_offset, w_mask);

    // Stage I: im2col -> fp16
    im2col_kernel<<<NPIX / 32, 256>>>(x);

    // Stage G: fp16 mma.sync GEMM + fused bias/sigmoid
    const int smem = NSTG * STGB;                      // 165888 B
    cudaFuncSetAttribute(gemm_f16, cudaFuncAttributeMaxDynamicSharedMemorySize, smem);
    gemm_f16<<<dim3(MPAD / MT, NPIX / NT), 512, smem>>>(b_offset, b_mask);

    // Stage D: deformable gather + group matmul
    deform_kernel<<<B_ * G_ * HO_, 128>>>(x, w_deform, out);
}

// round 6
// speedup vs baseline: 10.0934x; 1.0103x over previous
#include <cuda_runtime.h>
#include <cuda_fp16.h>
#include <cstdint>

// ---------------------------------------------------------------------------
// DCNv2 on GB300 (compute_103 PTX -> no tcgen05; fp16 mma.sync m16n8k16):
//   Stage P: pack weights -> g_wpack [1792, 1152] fp16
//   Stage I: im2col x -> g_cols [32768, 1152] fp16 (vectorized stores)
//   Stage G: fp16 mma.sync GEMM (fp32 accum), fused bias/sigmoid,
//            -> g_conv[b][oc][pix] in fp16
//   Stage D: bilinear deformable gather + per-group 2x2x9 matmul
// ---------------------------------------------------------------------------

#define B_      2
#define C_      128
#define H_      256
#define W_      256
#define HO_     128
#define WO_     128
#define G_      64
#define OC_OFF  1152
#define OC_ALL  1728
#define KDIM    1152
#define NPIX    32768
#define MPAD    1792

__device__ __align__(1024) __half g_conv[(size_t)B_ * OC_ALL * HO_ * WO_];
__device__ __align__(1024) __half g_cols[(size_t)NPIX * KDIM];
__device__ __align__(1024) __half g_wpack[(size_t)MPAD * KDIM];

// ------------------------------- helpers ----------------------------------
__device__ __forceinline__ uint32_t smem_u32(const void* p) {
    uint32_t a;
    asm("{ .reg .u64 t; cvta.to.shared.u64 t, %1; cvt.u32.u64 %0, t; }" : "=r"(a) : "l"(p));
    return a;
}
#define CP_ASYNC16(dst, src) \
    asm volatile("cp.async.cg.shared.global [%0], [%1], 16;" :: "r"(dst), "l"(src) : "memory")
#define CP_COMMIT() asm volatile("cp.async.commit_group;" ::: "memory")
#define CP_WAIT(n)  asm volatile("cp.async.wait_group %0;" :: "n"(n) : "memory")

#define LDSM_X4(r0, r1, r2, r3, addr)                                          \
    asm volatile("ldmatrix.sync.aligned.m8n8.x4.shared.b16 {%0,%1,%2,%3}, [%4];" \
        : "=r"(r0), "=r"(r1), "=r"(r2), "=r"(r3) : "r"(addr))

#define MMA_F16(d, a, b)                                                       \
    asm volatile("mma.sync.aligned.m16n8k16.row.col.f32.f16.f16.f32 "          \
        "{%0,%1,%2,%3}, {%4,%5,%6,%7}, {%8,%9}, {%0,%1,%2,%3};"                \
        : "+f"((d)[0]), "+f"((d)[1]), "+f"((d)[2]), "+f"((d)[3])               \
        : "r"((a)[0]), "r"((a)[1]), "r"((a)[2]), "r"((a)[3]),                  \
          "r"((b)[0]), "r"((b)[1]))

// ---------------------------------------------------------------------------
// Stage P: pack weights -> fp16. rows >= 1728 zero.
// ---------------------------------------------------------------------------
__global__ __launch_bounds__(256)
void pack_w(const float* __restrict__ wo, const float* __restrict__ wm)
{
    const size_t i = (size_t)blockIdx.x * 256 + threadIdx.x;
    if (i >= (size_t)MPAD * KDIM) return;
    const int row = (int)(i / KDIM);
    float v = 0.f;
    if (row < OC_OFF)      v = wo[i];
    else if (row < OC_ALL) v = wm[i - (size_t)OC_OFF * KDIM];
    g_wpack[i] = __float2half_rn(v);
}

// ---------------------------------------------------------------------------
// Stage I: im2col -> fp16, 8-byte vector stores.
// block = 256 thr = 32 wo x 8 c, 16 c-chunks.
// ---------------------------------------------------------------------------
__global__ __launch_bounds__(256)
void im2col_kernel(const float* __restrict__ x)
{
    __shared__ float st[32][73];
    const int t  = threadIdx.x;
    const int wl = t & 31;
    const int cl = t >> 5;
    const int n0 = blockIdx.x * 32;
    const int b  = n0 >> 14;
    const int ho = (n0 >> 7) & 127;
    const int wo = (n0 & 127) + wl;
    const int iy0 = 2 * ho - 1;
    const int ix0 = 2 * wo - 1;

    for (int cc = 0; cc < 16; ++cc) {
        const int c = cc * 8 + cl;
        const float* xp = x + (size_t)(b * C_ + c) * H_ * W_;
#pragma unroll
        for (int ky = 0; ky < 3; ++ky) {
            const int iy = iy0 + ky;
            const bool vy = (unsigned)iy < (unsigned)H_;
#pragma unroll
            for (int kx = 0; kx < 3; ++kx) {
                const int ix = ix0 + kx;
                float v = 0.f;
                if (vy && (unsigned)ix < (unsigned)W_) v = xp[iy * W_ + ix];
                st[wl][cl * 9 + ky * 3 + kx] = v;
            }
        }
        __syncthreads();
        // 32 rows x 18 quads (4 halfs = 8 B per store)
        for (int i = t; i < 32 * 18; i += 256) {
            const int r = i / 18, q = i - r * 18;
            const float* s = &st[r][q * 4];
            __half2 h01 = __floats2half2_rn(s[0], s[1]);
            __half2 h23 = __floats2half2_rn(s[2], s[3]);
            uint2 pk = make_uint2(*(uint32_t*)&h01, *(uint32_t*)&h23);
            *reinterpret_cast<uint2*>(
                &g_cols[(size_t)(n0 + r) * KDIM + cc * 72 + q * 4]) = pk;
        }
        __syncthreads();
    }
}

// ---------------------------------------------------------------------------
// Stage G: fp16 mma.sync GEMM.
//   CTA tile 128(M) x 256(N), 512 thr = 16 warps, warp tile 32x64.
//   K chunk = 64 halfs (4 k16 steps), 3-stage cp.async pipeline,
//   one syncthreads/iter, ldmatrix fragment loads. Output fp16.
// ---------------------------------------------------------------------------
#define MT      128
#define NT      256
#define KCH     64
#define NKC     18
#define NSTG    3
#define LDP     72          // row stride in halfs
#define ASF     (MT * LDP)
#define BSF     (NT * LDP)
#define STGH    (ASF + BSF)
#define STGB    (STGH * 2)

__global__ __launch_bounds__(512, 1)
void gemm_f16(const float* __restrict__ b_off, const float* __restrict__ b_msk)
{
    extern __shared__ __half sm[];

    const int tid  = threadIdx.x;
    const int wid  = tid >> 5;
    const int lane = tid & 31;
    const int wm   = wid & 3;
    const int wn   = wid >> 2;
    const int lm   = lane >> 2;
    const int lk   = lane & 3;
    const int g    = lane >> 3;
    const int li   = lane & 7;
    const int ocb  = blockIdx.x * MT;
    const int nb   = blockIdx.y * NT;

    const __half* Abase = g_wpack + (size_t)ocb * KDIM;
    const __half* Bbase = g_cols + (size_t)nb * KDIM;
    const uint32_t smb = smem_u32(sm);

    const uint32_t aoff = (uint32_t)((wm * 32 + (g & 1) * 8 + li) * LDP + (g >> 1) * 8) * 2;
    const uint32_t boff = (uint32_t)(ASF + (wn * 64 + (g >> 1) * 8 + li) * LDP + (g & 1) * 8) * 2;

    float d[2][8][4];
#pragma unroll
    for (int t = 0; t < 2; ++t)
#pragma unroll
        for (int nt = 0; nt < 8; ++nt)
#pragma unroll
            for (int j = 0; j < 4; ++j) d[t][nt][j] = 0.f;

    auto load_stage = [&](int kn) {
        const uint32_t stb = smb + (uint32_t)(kn % NSTG) * STGB;
        const __half* As = Abase + kn * KCH;
        const __half* Bs = Bbase + kn * KCH;
#pragma unroll
        for (int j = 0; j < 2; ++j) {
            const int i = tid + j * 512;
            const int r = i >> 3, c = i & 7;
            CP_ASYNC16(stb + (uint32_t)(r * LDP + c * 8) * 2,
                       As + (size_t)r * KDIM + c * 8);
        }
#pragma unroll
        for (int j = 0; j < 4; ++j) {
            const int i = tid + j * 512;
            const int r = i >> 3, c = i & 7;
            CP_ASYNC16(stb + (uint32_t)(ASF + r * LDP + c * 8) * 2,
                       Bs + (size_t)r * KDIM + c * 8);
        }
        CP_COMMIT();
    };

    load_stage(0);
    load_stage(1);

    for (int kc = 0; kc < NKC; ++kc) {
        CP_WAIT(1);
        __syncthreads();

        if (kc + 2 < NKC) load_stage(kc + 2);

        const uint32_t sb = smb + (uint32_t)(kc % NSTG) * STGB;

#pragma unroll
        for (int ks = 0; ks < 4; ++ks) {
            const uint32_t kb = (uint32_t)ks * 32;
            uint32_t a[2][4];
            LDSM_X4(a[0][0], a[0][1], a[0][2], a[0][3], sb + aoff + kb);
            LDSM_X4(a[1][0], a[1][1], a[1][2], a[1][3],
                    sb + aoff + 16 * LDP * 2 + kb);
            uint32_t bw[8][2];
#pragma unroll
            for (int np = 0; np < 4; ++np)
                LDSM_X4(bw[np * 2][0], bw[np * 2][1],
                        bw[np * 2 + 1][0], bw[np * 2 + 1][1],
                        sb + boff + (uint32_t)(np * 16 * LDP) * 2 + kb);
#pragma unroll
            for (int t = 0; t < 2; ++t)
#pragma unroll
                for (int nt = 0; nt < 8; ++nt)
                    MMA_F16(d[t][nt], a[t], bw[nt]);
        }
    }

    // ---- epilogue: bias (+sigmoid), fp16 __half2 coalesced stores ----
    const int b    = nb >> 14;
    const int pixb = nb & 16383;

#pragma unroll
    for (int t = 0; t < 2; ++t) {
        const int r0 = ocb + wm * 32 + t * 16 + lm;
#pragma unroll
        for (int half = 0; half < 2; ++half) {
            const int oc = r0 + half * 8;
            if (oc >= OC_ALL) continue;
            const bool msk = (oc >= OC_OFF);
            const float bias = msk ? b_msk[oc - OC_OFF] : b_off[oc];
            __half* rowp = g_conv + ((size_t)b * OC_ALL + oc) * 16384 + pixb;
#pragma unroll
            for (int nt = 0; nt < 8; ++nt) {
                const int col = wn * 64 + nt * 8 + 2 * lk;
                float v0 = d[t][nt][2 * half + 0] + bias;
                float v1 = d[t][nt][2 * half + 1] + bias;
                if (msk) {
                    v0 = 1.f / (1.f + __expf(-v0));
                    v1 = 1.f / (1.f + __expf(-v1));
                }
                *reinterpret_cast<__half2*>(rowp + col) = __floats2half2_rn(v0, v1);
            }
        }
    }
}

// ---------------------------------------------------------------------------
// Stage D: modulated deformable gather + per-group 2x2x9 matmul
// ---------------------------------------------------------------------------
__global__ __launch_bounds__(128)
void deform_kernel(const float* __restrict__ x,
                   const float* __restrict__ w_deform,
                   float* __restrict__ out)
{
    const int blk = blockIdx.x;
    const int ho  = blk & 127;
    const int g   = (blk >> 7) & 63;
    const int b   = blk >> 13;
    const int wo  = threadIdx.x;

    __shared__ float wd[2][2][9];
    if (threadIdx.x < 36) {
        const int o = threadIdx.x / 18;
        const int c = (threadIdx.x / 9) & 1;
        const int k = threadIdx.x % 9;
        wd[o][c][k] = w_deform[(((size_t)(g * 2 + o)) * 2 + c) * 9 + k];
    }
    __syncthreads();

    const float* xg0 = x + ((size_t)(b * C_ + g * 2) * H_) * W_;
    const float* xg1 = xg0 + (size_t)H_ * W_;

    const size_t CS  = (size_t)HO_ * WO_;
    const size_t pix = (size_t)ho * WO_ + wo;
    const __half* cv_b = g_conv + (size_t)b * OC_ALL * CS + pix;

    float acc0 = 0.f, acc1 = 0.f;

#pragma unroll
    for (int k = 0; k < 9; ++k) {
        const int choff = (g * 9 + k) * 2;
        const float dy = __half2float(cv_b[(size_t)choff * CS]);
        const float dx = __half2float(cv_b[(size_t)(choff + 1) * CS]);
        const float m  = __half2float(cv_b[(size_t)(OC_OFF + g * 9 + k) * CS]);

        const int ki = k / 3, kj = k - ki * 3;
        const float py = dy + (float)(2 * ho - 1 + ki);
        const float px = dx + (float)(2 * wo - 1 + kj);

        const float y0f = floorf(py), x0f = floorf(px);
        const float wy = py - y0f, wx = px - x0f;
        const int y0 = (int)y0f, x0 = (int)x0f;
        const int y1 = y0 + 1, x1 = x0 + 1;

        const bool vy0 = (unsigned)y0 < (unsigned)H_;
        const bool vy1 = (unsigned)y1 < (unsigned)H_;
        const bool vx0 = (unsigned)x0 < (unsigned)W_;
        const bool vx1 = (unsigned)x1 < (unsigned)W_;

        const float w00 = (1.f - wy) * (1.f - wx);
        const float w01 = (1.f - wy) * wx;
        const float w10 = wy * (1.f - wx);
        const float w11 = wy * wx;

        const int i00 = y0 * W_ + x0;
        const int i01 = y0 * W_ + x1;
        const int i10 = y1 * W_ + x0;
        const int i11 = y1 * W_ + x1;

        float s0 = 0.f, s1 = 0.f;
        if (vy0 && vx0) { s0 += w00 * xg0[i00]; s1 += w00 * xg1[i00]; }
        if (vy0 && vx1) { s0 += w01 * xg0[i01]; s1 += w01 * xg1[i01]; }
        if (vy1 && vx0) { s0 += w10 * xg0[i10]; s1 += w10 * xg1[i10]; }
        if (vy1 && vx1) { s0 += w11 * xg0[i11]; s1 += w11 * xg1[i11]; }

        s0 *= m; s1 *= m;
        acc0 = fmaf(s0, wd[0][0][k], acc0);
        acc0 = fmaf(s1, wd[0][1][k], acc0);
        acc1 = fmaf(s0, wd[1][0][k], acc1);
        acc1 = fmaf(s1, wd[1][1][k], acc1);
    }

    float* o0 = out + (((size_t)b * C_ + g * 2) * HO_ + ho) * WO_ + wo;
    o0[0]  = acc0;
    o0[CS] = acc1;
}

// ---------------------------------------------------------------------------
extern "C" void kernel_launch(void* const* d_in, const int* in_sizes, int n_in,
                              void* d_out, int out_size)
{
    const float* x        = (const float*)d_in[0];
    const float* w_offset = (const float*)d_in[1];
    const float* b_offset = (const float*)d_in[2];
    const float* w_mask   = (const float*)d_in[3];
    const float* b_mask   = (const float*)d_in[4];
    const float* w_deform = (const float*)d_in[5];
    float* out = (float*)d_out;

    const size_t wtot = (size_t)MPAD * KDIM;
    pack_w<<<(unsigned)((wtot + 255) / 256), 256>>>(w_offset, w_mask);

    im2col_kernel<<<NPIX / 32, 256>>>(x);

    const int smem = NSTG * STGB;
    cudaFuncSetAttribute(gemm_f16, cudaFuncAttributeMaxDynamicSharedMemorySize, smem);
    gemm_f16<<<dim3(MPAD / MT, NPIX / NT), 512, smem>>>(b_offset, b_mask);

    deform_kernel<<<B_ * G_ * HO_, 128>>>(x, w_deform, out);
}